// round 3
// baseline (speedup 1.0000x reference)
#include <cuda_runtime.h>
#include <math.h>

#define NN 8192
#define DD 1152
#define EE 262144

// -------- scratch (allocation-free: static device globals) --------
__device__ float g_q[(size_t)NN * DD];
__device__ float g_k[(size_t)NN * DD];
__device__ float g_v[(size_t)NN * DD];
__device__ float g_o[(size_t)NN * DD];

// -------- packed f32x2 helpers --------
typedef unsigned long long ull;

__device__ __forceinline__ void fma2(ull& acc, ull a, ull b) {
    asm("fma.rn.f32x2 %0, %1, %2, %0;" : "+l"(acc) : "l"(a), "l"(b));
}
__device__ __forceinline__ void mul2(ull& a, ull b) {
    asm("mul.rn.f32x2 %0, %0, %1;" : "+l"(a) : "l"(b));
}
__device__ __forceinline__ ull bcast2(float x) {
    ull r; asm("mov.b64 %0, {%1, %1};" : "=l"(r) : "f"(x)); return r;
}
__device__ __forceinline__ ull pack2(float lo, float hi) {
    ull r; asm("mov.b64 %0, {%1, %2};" : "=l"(r) : "f"(lo), "f"(hi)); return r;
}
__device__ __forceinline__ void unpack2(ull v, float& lo, float& hi) {
    asm("mov.b64 {%0, %1}, %2;" : "=f"(lo), "=f"(hi) : "l"(v));
}

// ====================== rot kernel ======================
__global__ void rot_kernel(const float* __restrict__ ev,
                           const float* __restrict__ er,
                           float* __restrict__ rot)
{
    int e = blockIdx.x * 256 + threadIdx.x;
    if (e >= EE) return;
    float vx = ev[3*e+0], vy = ev[3*e+1], vz = ev[3*e+2];
    float dist = sqrtf(vx*vx + vy*vy + vz*vz);
    float nx0 = vx/dist, nx1 = vy/dist, nx2 = vz/dist;

    float r0 = er[3*e+0]-0.5f, r1 = er[3*e+1]-0.5f, r2 = er[3*e+2]-0.5f;
    float rn = sqrtf(r0*r0 + r1*r1 + r2*r2);
    float a0 = r0/rn, a1 = r1/rn, a2 = r2/rn;
    float b0 = -a1, b1 = a0, b2 = a2;
    float c0 = a0, c1 = -a2, c2 = a1;

    float da = fabsf(a0*nx0 + a1*nx1 + a2*nx2);
    float db = fabsf(b0*nx0 + b1*nx1 + b2*nx2);
    float dc = fabsf(c0*nx0 + c1*nx1 + c2*nx2);

    float e0 = a0, e1 = a1, e2c_ = a2, dcur = da;
    if (dcur > db) { e0 = b0; e1 = b1; e2c_ = b2; dcur = db; }
    if (dcur > dc) { e0 = c0; e1 = c1; e2c_ = c2; }

    float z0 = nx1*e2c_ - nx2*e1;
    float z1 = nx2*e0   - nx0*e2c_;
    float z2 = nx0*e1   - nx1*e0;
    float zn = sqrtf(z0*z0 + z1*z1 + z2*z2);
    z0 /= zn; z1 /= zn; z2 /= zn;
    float y0 = nx1*z2 - nx2*z1;
    float y1 = nx2*z0 - nx0*z2;
    float y2 = nx0*z1 - nx1*z0;
    float yn = sqrtf(y0*y0 + y1*y1 + y2*y2);
    y0 /= yn; y1 /= yn; y2 /= yn;

    float* R = rot + (size_t)e * 9;
    R[0] =  z0; R[1] =  z1; R[2] =  z2;
    R[3] = nx0; R[4] = nx1; R[5] = nx2;
    R[6] = -y0; R[7] = -y1; R[8] = -y2;
}

// ====================== irreps linear ======================
// 8 nodes, 64 outputs per block; 128 threads = 8(ty nodes) x 16(tx -> 4 outs).
template<int L>
__global__ void __launch_bounds__(128) linear_kernel(const float* __restrict__ x,
                                                     const float* __restrict__ W,
                                                     float* __restrict__ y)
{
    constexpr int d = 2*L + 1;
    constexpr int s = (L == 0) ? 0 : (L == 1 ? 128 : 512);
    constexpr int rowlen = 128 * d;

    extern __shared__ float sm[];
    float* Ws  = sm;            // [128][68]: Ws[c*68+oo] = W[l][obase+oo][c]
    float* XsT = sm + 128*68;   // [8*d][128]

    const int tid = threadIdx.x;
    const int n0  = blockIdx.x * 8;
    const int obase = blockIdx.y * 64;

    const float* Wl = W + L * 16384 + obase * 128;
    for (int idx = tid; idx < 8192; idx += 128) {
        int o = idx >> 7, c = idx & 127;
        Ws[c*68 + o] = Wl[o*128 + c];
    }
    for (int i = tid; i < 8 * (rowlen/4); i += 128) {
        int n = i / (rowlen/4);
        int p = (i % (rowlen/4)) * 4;
        float4 v4 = *(const float4*)&x[(size_t)(n0+n)*DD + s + p];
        float vv[4] = {v4.x, v4.y, v4.z, v4.w};
        #pragma unroll
        for (int e = 0; e < 4; e++) {
            int pp = p + e, c = pp / d, m = pp - c * d;
            XsT[(n*d + m)*128 + c] = vv[e];
        }
    }
    __syncthreads();

    const int ty = tid >> 4, tx = tid & 15;
    ull acc[d][2];
    #pragma unroll
    for (int m = 0; m < d; m++) { acc[m][0] = 0ull; acc[m][1] = 0ull; }

    const float* Xbase = XsT + ty * d * 128;
    for (int c = 0; c < 128; c += 4) {
        float4 xa[d];
        #pragma unroll
        for (int m = 0; m < d; m++) xa[m] = *(const float4*)&Xbase[m*128 + c];
        #pragma unroll
        for (int cc = 0; cc < 4; cc++) {
            float4 w = *(const float4*)&Ws[(c+cc)*68 + tx*4];
            ull w01 = pack2(w.x, w.y), w23 = pack2(w.z, w.w);
            #pragma unroll
            for (int m = 0; m < d; m++) {
                ull xb = bcast2(((const float*)&xa[m])[cc]);
                fma2(acc[m][0], xb, w01);
                fma2(acc[m][1], xb, w23);
            }
        }
    }

    const float scale = 0.08838834764831845f;  // 1/sqrt(128)
    float* yrow = y + (size_t)(n0 + ty) * DD + s;
    #pragma unroll
    for (int m = 0; m < d; m++) {
        #pragma unroll
        for (int jp = 0; jp < 2; jp++) {
            float f0, f1; unpack2(acc[m][jp], f0, f1);
            int o = obase + tx*4 + jp*2;
            yrow[(o  )*d + m] = f0 * scale;
            yrow[(o+1)*d + m] = f1 * scale;
        }
    }
}

// ====================== flash attention (f32x2) ======================
// grid (16 q-tiles, 128 b*h). BM=32, BK=64, hd=144 (pad 160 for V).
// 128 threads = 8(ty: 4 q-rows) x 16(tx: 4 k-cols in S / 10 O-cols in PV)
// smem 110080 B -> 2 CTAs/SM.
__global__ void __launch_bounds__(128) attn_kernel(const float* __restrict__ q,
                                                   const float* __restrict__ k,
                                                   const float* __restrict__ v,
                                                   float* __restrict__ o)
{
    extern __shared__ float sm[];
    float* QsT = sm;               // [144][36]
    float* KsT = QsT + 144*36;     // [144][68]
    float* Vs  = KsT + 144*68;     // [64][160]  (cols 144..159 = 0 pad)
    float* PsT = Vs  + 64*160;     // [64 kk][36 rows]

    const int tid = threadIdx.x;
    const int ty = tid >> 4, tx = tid & 15;
    const int b = blockIdx.y >> 3, h = blockIdx.y & 7;
    const int q0 = blockIdx.x * 32;
    const size_t hoff  = (size_t)h * 144;
    const size_t bbase = (size_t)b * 512;

    const float qscale = 1.0f / 12.0f;  // 1/sqrt(144)
    for (int f = tid; f < 32*36; f += 128) {
        int row = f / 36, cs = (f % 36) * 4;
        float4 qa = *(const float4*)&q[(bbase + q0 + row) * DD + hoff + cs];
        QsT[(cs+0)*36 + row] = qa.x * qscale;
        QsT[(cs+1)*36 + row] = qa.y * qscale;
        QsT[(cs+2)*36 + row] = qa.z * qscale;
        QsT[(cs+3)*36 + row] = qa.w * qscale;
    }
    // zero V pad (cols 144..159 of 64 rows): 256 float4 stores
    for (int f = tid; f < 256; f += 128) {
        int row = f >> 2, cs = 144 + (f & 3) * 4;
        *(float4*)&Vs[row*160 + cs] = make_float4(0.f, 0.f, 0.f, 0.f);
    }

    float m_i[4], l_i[4];
    ull oacc[4][5];
    #pragma unroll
    for (int i = 0; i < 4; i++) {
        m_i[i] = -1e30f; l_i[i] = 0.f;
        #pragma unroll
        for (int jp = 0; jp < 5; jp++) oacc[i][jp] = 0ull;
    }

    for (int kt = 0; kt < 512; kt += 64) {
        __syncthreads();
        for (int f = tid; f < 64*36; f += 128) {
            int row = f / 36, cs = (f % 36) * 4;
            size_t g = (bbase + kt + row) * (size_t)DD + hoff + cs;
            float4 ka = *(const float4*)&k[g];
            KsT[(cs+0)*68 + row] = ka.x;
            KsT[(cs+1)*68 + row] = ka.y;
            KsT[(cs+2)*68 + row] = ka.z;
            KsT[(cs+3)*68 + row] = ka.w;
            float4 va = *(const float4*)&v[g];
            *(float4*)&Vs[row*160 + cs] = va;
        }
        __syncthreads();

        // ---- S = Q K^T ----
        ull s2[4][2];
        #pragma unroll
        for (int i = 0; i < 4; i++) { s2[i][0] = 0ull; s2[i][1] = 0ull; }

        #pragma unroll 2
        for (int c = 0; c < 144; c++) {
            float4 qa = *(const float4*)&QsT[c*36 + 4*ty];
            float4 kb = *(const float4*)&KsT[c*68 + 4*tx];
            ull k01 = pack2(kb.x, kb.y), k23 = pack2(kb.z, kb.w);
            #pragma unroll
            for (int i = 0; i < 4; i++) {
                ull qb = bcast2(((const float*)&qa)[i]);
                fma2(s2[i][0], qb, k01);
                fma2(s2[i][1], qb, k23);
            }
        }

        // ---- online softmax (16-lane reduce, stays within half-warp) ----
        float p_[4][4];
        #pragma unroll
        for (int i = 0; i < 4; i++) {
            float s_[4];
            unpack2(s2[i][0], s_[0], s_[1]);
            unpack2(s2[i][1], s_[2], s_[3]);
            float rm = fmaxf(fmaxf(s_[0], s_[1]), fmaxf(s_[2], s_[3]));
            #pragma unroll
            for (int off = 8; off; off >>= 1)
                rm = fmaxf(rm, __shfl_xor_sync(0xffffffffu, rm, off));
            float newm = fmaxf(m_i[i], rm);
            float rs = 0.f;
            #pragma unroll
            for (int j = 0; j < 4; j++) { p_[i][j] = __expf(s_[j] - newm); rs += p_[i][j]; }
            #pragma unroll
            for (int off = 8; off; off >>= 1)
                rs += __shfl_xor_sync(0xffffffffu, rs, off);
            float corr = __expf(m_i[i] - newm);
            l_i[i] = l_i[i] * corr + rs;
            m_i[i] = newm;
            ull cb = bcast2(corr);
            #pragma unroll
            for (int jp = 0; jp < 5; jp++) mul2(oacc[i][jp], cb);
        }
        #pragma unroll
        for (int j = 0; j < 4; j++) {
            *(float4*)&PsT[(4*tx + j)*36 + 4*ty] =
                make_float4(p_[0][j], p_[1][j], p_[2][j], p_[3][j]);
        }
        __syncthreads();

        // ---- O += P V ----
        #pragma unroll 2
        for (int kk = 0; kk < 64; kk++) {
            float4 pr = *(const float4*)&PsT[kk*36 + 4*ty];
            const float* vrow = &Vs[kk*160 + tx*10];
            ull vv[5];
            #pragma unroll
            for (int jp = 0; jp < 5; jp++)
                vv[jp] = *(const ull*)&vrow[2*jp];
            #pragma unroll
            for (int i = 0; i < 4; i++) {
                ull pb = bcast2(((const float*)&pr)[i]);
                #pragma unroll
                for (int jp = 0; jp < 5; jp++)
                    fma2(oacc[i][jp], pb, vv[jp]);
            }
        }
    }

    #pragma unroll
    for (int i = 0; i < 4; i++) {
        float inv = 1.0f / l_i[i];
        float* obase = o + (bbase + q0 + 4*ty + i) * (size_t)DD + hoff;
        #pragma unroll
        for (int jp = 0; jp < 5; jp++) {
            float f0, f1; unpack2(oacc[i][jp], f0, f1);
            int c0 = tx*10 + 2*jp;
            if (c0   < 144) obase[c0  ] = f0 * inv;
            if (c0+1 < 144) obase[c0+1] = f1 * inv;
        }
    }
}

// ====================== epilogue ======================
__global__ void __launch_bounds__(256) epilogue_kernel(const float* __restrict__ x,
                                                       const float* __restrict__ attn,
                                                       const float* __restrict__ gamma,
                                                       const float* __restrict__ beta,
                                                       float* __restrict__ out)
{
    const int n = blockIdx.x;
    const int tid = threadIdx.x;
    const size_t base = (size_t)n * DD;

    __shared__ float red[8];
    __shared__ float mu_s, rv_s;

    float val = 0.f;
    if (tid < 128) val = x[base + tid] + attn[base + tid];
    float s1 = val, s2 = val * val;
    #pragma unroll
    for (int off = 16; off; off >>= 1) {
        s1 += __shfl_xor_sync(0xffffffffu, s1, off);
        s2 += __shfl_xor_sync(0xffffffffu, s2, off);
    }
    if (tid < 128 && (tid & 31) == 0) { red[(tid>>5)*2] = s1; red[(tid>>5)*2+1] = s2; }
    __syncthreads();
    if (tid == 0) {
        float t1 = red[0] + red[2] + red[4] + red[6];
        float t2 = red[1] + red[3] + red[5] + red[7];
        float mu = t1 * (1.f/128.f);
        float var = t2 * (1.f/128.f) - mu*mu;
        mu_s = mu;
        rv_s = rsqrtf(var + 1e-5f);
    }
    __syncthreads();
    const float mu = mu_s, rv = rv_s;

    for (int i = tid; i < DD; i += 256) {
        float vv = x[base + i] + attn[base + i];
        if (i < 128) {
            float z = (vv - mu) * rv * gamma[i] + beta[i];
            vv = z / (1.f + __expf(-z));
        }
        out[base + i] = vv;
    }
}

// ====================== launch ======================
extern "C" void kernel_launch(void* const* d_in, const int* in_sizes, int n_in,
                              void* d_out, int out_size)
{
    const float* x     = (const float*)d_in[0];
    const float* ev    = (const float*)d_in[1];
    const float* er    = (const float*)d_in[2];
    const float* Wq    = (const float*)d_in[3];
    const float* Wk    = (const float*)d_in[4];
    const float* Wv    = (const float*)d_in[5];
    const float* Wo    = (const float*)d_in[6];
    const float* gamma = (const float*)d_in[7];
    const float* beta  = (const float*)d_in[8];
    float* out  = (float*)d_out;
    float* rotp = out + (size_t)NN * DD;

    float *qp, *kp, *vp, *op;
    cudaGetSymbolAddress((void**)&qp, g_q);
    cudaGetSymbolAddress((void**)&kp, g_k);
    cudaGetSymbolAddress((void**)&vp, g_v);
    cudaGetSymbolAddress((void**)&op, g_o);

    const int SM0 = 128*68*4 + 8*128*4;                        // 38912
    const int SM1 = 128*68*4 + 8*384*4;                        // 47104
    const int SM2 = 128*68*4 + 8*640*4;                        // 55296
    const int SMA = (144*36 + 144*68 + 64*160 + 64*36) * 4;    // 110080

    cudaFuncSetAttribute((const void*)linear_kernel<0>, cudaFuncAttributeMaxDynamicSharedMemorySize, SM0);
    cudaFuncSetAttribute((const void*)linear_kernel<1>, cudaFuncAttributeMaxDynamicSharedMemorySize, SM1);
    cudaFuncSetAttribute((const void*)linear_kernel<2>, cudaFuncAttributeMaxDynamicSharedMemorySize, SM2);
    cudaFuncSetAttribute((const void*)attn_kernel,      cudaFuncAttributeMaxDynamicSharedMemorySize, SMA);

    rot_kernel<<<EE/256, 256>>>(ev, er, rotp);

    dim3 lgrid(NN/8, 2);
    linear_kernel<0><<<lgrid, 128, SM0>>>(x, Wq, qp);
    linear_kernel<1><<<lgrid, 128, SM1>>>(x, Wq, qp);
    linear_kernel<2><<<lgrid, 128, SM2>>>(x, Wq, qp);
    linear_kernel<0><<<lgrid, 128, SM0>>>(x, Wk, kp);
    linear_kernel<1><<<lgrid, 128, SM1>>>(x, Wk, kp);
    linear_kernel<2><<<lgrid, 128, SM2>>>(x, Wk, kp);
    linear_kernel<0><<<lgrid, 128, SM0>>>(x, Wv, vp);
    linear_kernel<1><<<lgrid, 128, SM1>>>(x, Wv, vp);
    linear_kernel<2><<<lgrid, 128, SM2>>>(x, Wv, vp);

    attn_kernel<<<dim3(16, 128), 128, SMA>>>(qp, kp, vp, op);

    linear_kernel<0><<<lgrid, 128, SM0>>>(op, Wo, kp);
    linear_kernel<1><<<lgrid, 128, SM1>>>(op, Wo, kp);
    linear_kernel<2><<<lgrid, 128, SM2>>>(op, Wo, kp);

    epilogue_kernel<<<NN, 256>>>(x, kp, gamma, beta, out);
}

// round 4
// speedup vs baseline: 1.6159x; 1.6159x over previous
#include <cuda_runtime.h>
#include <math.h>

#define NN 8192
#define DD 1152
#define EE 262144

typedef unsigned int uint32;
typedef unsigned long long ull;

// -------- scratch (allocation-free: static device globals) --------
__device__ float g_q[(size_t)NN * DD];
__device__ float g_k[(size_t)NN * DD];
__device__ float g_v[(size_t)NN * DD];
__device__ float g_o[(size_t)NN * DD];

// -------- packed f32x2 helpers (linears) --------
__device__ __forceinline__ void fma2(ull& acc, ull a, ull b) {
    asm("fma.rn.f32x2 %0, %1, %2, %0;" : "+l"(acc) : "l"(a), "l"(b));
}
__device__ __forceinline__ ull bcast2(float x) {
    ull r; asm("mov.b64 %0, {%1, %1};" : "=l"(r) : "f"(x)); return r;
}
__device__ __forceinline__ ull pack2(float lo, float hi) {
    ull r; asm("mov.b64 %0, {%1, %2};" : "=l"(r) : "f"(lo), "f"(hi)); return r;
}
__device__ __forceinline__ void unpack2(ull v, float& lo, float& hi) {
    asm("mov.b64 {%0, %1}, %2;" : "=f"(lo), "=f"(hi) : "l"(v));
}

// -------- tf32 mma helpers (attention) --------
__device__ __forceinline__ float tf32r(float x) {
    uint32 r; asm("cvt.rna.tf32.f32 %0, %1;" : "=r"(r) : "f"(x));
    return __uint_as_float(r);
}
__device__ __forceinline__ void mma_tf32(float* d,
                                         uint32 a0, uint32 a1, uint32 a2, uint32 a3,
                                         uint32 b0, uint32 b1) {
    asm("mma.sync.aligned.m16n8k8.row.col.f32.tf32.tf32.f32 "
        "{%0,%1,%2,%3}, {%4,%5,%6,%7}, {%8,%9}, {%0,%1,%2,%3};"
        : "+f"(d[0]), "+f"(d[1]), "+f"(d[2]), "+f"(d[3])
        : "r"(a0), "r"(a1), "r"(a2), "r"(a3), "r"(b0), "r"(b1));
}

// ====================== rot kernel ======================
__global__ void rot_kernel(const float* __restrict__ ev,
                           const float* __restrict__ er,
                           float* __restrict__ rot)
{
    int e = blockIdx.x * 256 + threadIdx.x;
    if (e >= EE) return;
    float vx = ev[3*e+0], vy = ev[3*e+1], vz = ev[3*e+2];
    float dist = sqrtf(vx*vx + vy*vy + vz*vz);
    float nx0 = vx/dist, nx1 = vy/dist, nx2 = vz/dist;

    float r0 = er[3*e+0]-0.5f, r1 = er[3*e+1]-0.5f, r2 = er[3*e+2]-0.5f;
    float rn = sqrtf(r0*r0 + r1*r1 + r2*r2);
    float a0 = r0/rn, a1 = r1/rn, a2 = r2/rn;
    float b0 = -a1, b1 = a0, b2 = a2;
    float c0 = a0, c1 = -a2, c2 = a1;

    float da = fabsf(a0*nx0 + a1*nx1 + a2*nx2);
    float db = fabsf(b0*nx0 + b1*nx1 + b2*nx2);
    float dc = fabsf(c0*nx0 + c1*nx1 + c2*nx2);

    float e0 = a0, e1 = a1, e2c_ = a2, dcur = da;
    if (dcur > db) { e0 = b0; e1 = b1; e2c_ = b2; dcur = db; }
    if (dcur > dc) { e0 = c0; e1 = c1; e2c_ = c2; }

    float z0 = nx1*e2c_ - nx2*e1;
    float z1 = nx2*e0   - nx0*e2c_;
    float z2 = nx0*e1   - nx1*e0;
    float zn = sqrtf(z0*z0 + z1*z1 + z2*z2);
    z0 /= zn; z1 /= zn; z2 /= zn;
    float y0 = nx1*z2 - nx2*z1;
    float y1 = nx2*z0 - nx0*z2;
    float y2 = nx0*z1 - nx1*z0;
    float yn = sqrtf(y0*y0 + y1*y1 + y2*y2);
    y0 /= yn; y1 /= yn; y2 /= yn;

    float* R = rot + (size_t)e * 9;
    R[0] =  z0; R[1] =  z1; R[2] =  z2;
    R[3] = nx0; R[4] = nx1; R[5] = nx2;
    R[6] = -y0; R[7] = -y1; R[8] = -y2;
}

// ====================== irreps linear (round-2 config) ======================
template<int L>
__global__ void __launch_bounds__(256) linear_kernel(const float* __restrict__ x,
                                                     const float* __restrict__ W,
                                                     float* __restrict__ y)
{
    constexpr int d = 2*L + 1;
    constexpr int s = (L == 0) ? 0 : (L == 1 ? 128 : 512);
    constexpr int rowlen = 128 * d;

    extern __shared__ float sm[];
    float* Ws  = sm;            // [128][68]
    float* XsT = sm + 128*68;   // [16*d][128]

    const int tid = threadIdx.x;
    const int n0  = blockIdx.x * 16;
    const int obase = blockIdx.y * 64;

    const float* Wl = W + L * 16384 + obase * 128;
    for (int idx = tid; idx < 8192; idx += 256) {
        int o = idx >> 7, c = idx & 127;
        Ws[c*68 + o] = Wl[o*128 + c];
    }
    for (int i = tid; i < 16 * (rowlen/4); i += 256) {
        int n = i / (rowlen/4);
        int p = (i % (rowlen/4)) * 4;
        float4 v4 = *(const float4*)&x[(size_t)(n0+n)*DD + s + p];
        float vv[4] = {v4.x, v4.y, v4.z, v4.w};
        #pragma unroll
        for (int e = 0; e < 4; e++) {
            int pp = p + e, c = pp / d, m = pp - c * d;
            XsT[(n*d + m)*128 + c] = vv[e];
        }
    }
    __syncthreads();

    const int ty = tid >> 4, tx = tid & 15;
    ull acc[d][2];
    #pragma unroll
    for (int m = 0; m < d; m++) { acc[m][0] = 0ull; acc[m][1] = 0ull; }

    const float* Xbase = XsT + ty * d * 128;
    for (int c = 0; c < 128; c += 4) {
        float4 xa[d];
        #pragma unroll
        for (int m = 0; m < d; m++) xa[m] = *(const float4*)&Xbase[m*128 + c];
        #pragma unroll
        for (int cc = 0; cc < 4; cc++) {
            float4 w = *(const float4*)&Ws[(c+cc)*68 + tx*4];
            ull w01 = pack2(w.x, w.y), w23 = pack2(w.z, w.w);
            #pragma unroll
            for (int m = 0; m < d; m++) {
                ull xb = bcast2(((const float*)&xa[m])[cc]);
                fma2(acc[m][0], xb, w01);
                fma2(acc[m][1], xb, w23);
            }
        }
    }

    const float scale = 0.08838834764831845f;
    float* yrow = y + (size_t)(n0 + ty) * DD + s;
    #pragma unroll
    for (int m = 0; m < d; m++) {
        #pragma unroll
        for (int jp = 0; jp < 2; jp++) {
            float f0, f1; unpack2(acc[m][jp], f0, f1);
            int o = obase + tx*4 + jp*2;
            yrow[(o  )*d + m] = f0 * scale;
            yrow[(o+1)*d + m] = f1 * scale;
        }
    }
}

// ====================== flash attention (TF32 mma.sync) ======================
// grid (8 q-tiles, 128 b*h); 128 threads = 4 warps, 16 q-rows/warp, 32-key tiles.
// smem pitches chosen conflict-free: PQ=148(≡20), PV=44(≡12), PP=52(≡20) mod 32.
#define PQ 148
#define PV 44
#define PP 52

__global__ void __launch_bounds__(128) attn_kernel(const float* __restrict__ q,
                                                   const float* __restrict__ k,
                                                   const float* __restrict__ v,
                                                   float* __restrict__ o)
{
    extern __shared__ float sm[];
    float* Qs  = sm;               // [64][148]
    float* Ks  = Qs  + 64*PQ;      // [32][148]
    float* VsT = Ks  + 32*PQ;      // [144][44]
    float* Ps  = VsT + 144*PV;     // [64][52]

    const int tid  = threadIdx.x;
    const int wid  = tid >> 5, lane = tid & 31;
    const int gr   = lane >> 2, th = lane & 3;   // groupID, threadInGroup
    const int b    = blockIdx.y >> 3, h = blockIdx.y & 7;
    const int q0   = blockIdx.x * 64;
    const size_t hoff  = (size_t)h * 144;
    const size_t bbase = (size_t)b * 512;

    const float qscale = 1.0f / 12.0f;
    for (int f = tid; f < 64*36; f += 128) {
        int row = f / 36, cs = (f % 36) * 4;
        float4 qa = *(const float4*)&q[(bbase + q0 + row) * DD + hoff + cs];
        Qs[row*PQ + cs+0] = tf32r(qa.x * qscale);
        Qs[row*PQ + cs+1] = tf32r(qa.y * qscale);
        Qs[row*PQ + cs+2] = tf32r(qa.z * qscale);
        Qs[row*PQ + cs+3] = tf32r(qa.w * qscale);
    }

    float m_i[2] = {-1e30f, -1e30f};
    float l_i[2] = {0.f, 0.f};
    float oac[18][4];
    #pragma unroll
    for (int nt = 0; nt < 18; nt++)
        #pragma unroll
        for (int j = 0; j < 4; j++) oac[nt][j] = 0.f;

    const int warpRow = 16 * wid;   // warp's first q-row within tile

    for (int kt = 0; kt < 512; kt += 32) {
        __syncthreads();
        for (int f = tid; f < 32*36; f += 128) {
            int row = f / 36, cs = (f % 36) * 4;
            size_t g = (bbase + kt + row) * (size_t)DD + hoff + cs;
            float4 ka = *(const float4*)&k[g];
            Ks[row*PQ + cs+0] = tf32r(ka.x);
            Ks[row*PQ + cs+1] = tf32r(ka.y);
            Ks[row*PQ + cs+2] = tf32r(ka.z);
            Ks[row*PQ + cs+3] = tf32r(ka.w);
            float4 va = *(const float4*)&v[g];
            VsT[(cs+0)*PV + row] = tf32r(va.x);
            VsT[(cs+1)*PV + row] = tf32r(va.y);
            VsT[(cs+2)*PV + row] = tf32r(va.z);
            VsT[(cs+3)*PV + row] = tf32r(va.w);
        }
        __syncthreads();

        // ---- S = Q K^T : 4 key n-tiles x 18 k-steps ----
        float s_[4][4];
        #pragma unroll
        for (int nt = 0; nt < 4; nt++)
            #pragma unroll
            for (int j = 0; j < 4; j++) s_[nt][j] = 0.f;

        #pragma unroll 3
        for (int ks = 0; ks < 18; ks++) {
            int k0 = ks * 8;
            const float* Qr = Qs + k0 + th;
            uint32 a0 = __float_as_uint(Qr[(warpRow + gr     ) * PQ    ]);
            uint32 a1 = __float_as_uint(Qr[(warpRow + gr + 8 ) * PQ    ]);
            uint32 a2 = __float_as_uint(Qr[(warpRow + gr     ) * PQ + 4]);
            uint32 a3 = __float_as_uint(Qr[(warpRow + gr + 8 ) * PQ + 4]);
            #pragma unroll
            for (int nt = 0; nt < 4; nt++) {
                const float* Kr = Ks + (nt*8 + gr) * PQ + k0 + th;
                uint32 b0 = __float_as_uint(Kr[0]);
                uint32 b1 = __float_as_uint(Kr[4]);
                mma_tf32(s_[nt], a0, a1, a2, a3, b0, b1);
            }
        }

        // ---- online softmax: row halves r=0 (rows gr), r=1 (rows gr+8) ----
        #pragma unroll
        for (int r = 0; r < 2; r++) {
            float rm = -1e30f;
            #pragma unroll
            for (int nt = 0; nt < 4; nt++)
                rm = fmaxf(rm, fmaxf(s_[nt][2*r], s_[nt][2*r+1]));
            rm = fmaxf(rm, __shfl_xor_sync(0xffffffffu, rm, 1));
            rm = fmaxf(rm, __shfl_xor_sync(0xffffffffu, rm, 2));
            float newm = fmaxf(m_i[r], rm);
            float rs = 0.f;
            #pragma unroll
            for (int nt = 0; nt < 4; nt++) {
                float p0 = __expf(s_[nt][2*r  ] - newm);
                float p1 = __expf(s_[nt][2*r+1] - newm);
                s_[nt][2*r] = p0; s_[nt][2*r+1] = p1;
                rs += p0 + p1;
            }
            rs += __shfl_xor_sync(0xffffffffu, rs, 1);
            rs += __shfl_xor_sync(0xffffffffu, rs, 2);
            float corr = __expf(m_i[r] - newm);
            l_i[r] = l_i[r] * corr + rs;
            m_i[r] = newm;
            #pragma unroll
            for (int nt = 0; nt < 18; nt++) {
                oac[nt][2*r  ] *= corr;
                oac[nt][2*r+1] *= corr;
            }
        }

        // ---- store P (per-warp rows, only warp-sync needed) ----
        #pragma unroll
        for (int nt = 0; nt < 4; nt++) {
            int col = nt*8 + 2*th;
            Ps[(warpRow + gr    ) * PP + col    ] = tf32r(s_[nt][0]);
            Ps[(warpRow + gr    ) * PP + col + 1] = tf32r(s_[nt][1]);
            Ps[(warpRow + gr + 8) * PP + col    ] = tf32r(s_[nt][2]);
            Ps[(warpRow + gr + 8) * PP + col + 1] = tf32r(s_[nt][3]);
        }
        __syncwarp();

        // ---- O += P V : 4 k-steps x 18 dim n-tiles ----
        #pragma unroll
        for (int ks = 0; ks < 4; ks++) {
            int k0 = ks * 8;
            const float* Pr = Ps + k0 + th;
            uint32 a0 = __float_as_uint(Pr[(warpRow + gr    ) * PP    ]);
            uint32 a1 = __float_as_uint(Pr[(warpRow + gr + 8) * PP    ]);
            uint32 a2 = __float_as_uint(Pr[(warpRow + gr    ) * PP + 4]);
            uint32 a3 = __float_as_uint(Pr[(warpRow + gr + 8) * PP + 4]);
            #pragma unroll
            for (int nt = 0; nt < 18; nt++) {
                const float* Vr = VsT + (nt*8 + gr) * PV + k0 + th;
                uint32 b0 = __float_as_uint(Vr[0]);
                uint32 b1 = __float_as_uint(Vr[4]);
                mma_tf32(oac[nt], a0, a1, a2, a3, b0, b1);
            }
        }
    }

    // ---- epilogue: divide by l, write ----
    #pragma unroll
    for (int r = 0; r < 2; r++) {
        float inv = 1.0f / l_i[r];
        int row = q0 + warpRow + gr + 8*r;
        float* ob = o + (bbase + row) * (size_t)DD + hoff;
        #pragma unroll
        for (int nt = 0; nt < 18; nt++) {
            int col = nt*8 + 2*th;
            ob[col    ] = oac[nt][2*r  ] * inv;
            ob[col + 1] = oac[nt][2*r+1] * inv;
        }
    }
}

// ====================== epilogue ======================
__global__ void __launch_bounds__(256) epilogue_kernel(const float* __restrict__ x,
                                                       const float* __restrict__ attn,
                                                       const float* __restrict__ gamma,
                                                       const float* __restrict__ beta,
                                                       float* __restrict__ out)
{
    const int n = blockIdx.x;
    const int tid = threadIdx.x;
    const size_t base = (size_t)n * DD;

    __shared__ float red[8];
    __shared__ float mu_s, rv_s;

    float val = 0.f;
    if (tid < 128) val = x[base + tid] + attn[base + tid];
    float s1 = val, s2 = val * val;
    #pragma unroll
    for (int off = 16; off; off >>= 1) {
        s1 += __shfl_xor_sync(0xffffffffu, s1, off);
        s2 += __shfl_xor_sync(0xffffffffu, s2, off);
    }
    if (tid < 128 && (tid & 31) == 0) { red[(tid>>5)*2] = s1; red[(tid>>5)*2+1] = s2; }
    __syncthreads();
    if (tid == 0) {
        float t1 = red[0] + red[2] + red[4] + red[6];
        float t2 = red[1] + red[3] + red[5] + red[7];
        float mu = t1 * (1.f/128.f);
        float var = t2 * (1.f/128.f) - mu*mu;
        mu_s = mu;
        rv_s = rsqrtf(var + 1e-5f);
    }
    __syncthreads();
    const float mu = mu_s, rv = rv_s;

    for (int i = tid; i < DD; i += 256) {
        float vv = x[base + i] + attn[base + i];
        if (i < 128) {
            float z = (vv - mu) * rv * gamma[i] + beta[i];
            vv = z / (1.f + __expf(-z));
        }
        out[base + i] = vv;
    }
}

// ====================== launch ======================
extern "C" void kernel_launch(void* const* d_in, const int* in_sizes, int n_in,
                              void* d_out, int out_size)
{
    const float* x     = (const float*)d_in[0];
    const float* ev    = (const float*)d_in[1];
    const float* er    = (const float*)d_in[2];
    const float* Wq    = (const float*)d_in[3];
    const float* Wk    = (const float*)d_in[4];
    const float* Wv    = (const float*)d_in[5];
    const float* Wo    = (const float*)d_in[6];
    const float* gamma = (const float*)d_in[7];
    const float* beta  = (const float*)d_in[8];
    float* out  = (float*)d_out;
    float* rotp = out + (size_t)NN * DD;

    float *qp, *kp, *vp, *op;
    cudaGetSymbolAddress((void**)&qp, g_q);
    cudaGetSymbolAddress((void**)&kp, g_k);
    cudaGetSymbolAddress((void**)&vp, g_v);
    cudaGetSymbolAddress((void**)&op, g_o);

    const int SM0 = 128*68*4 + 16*128*4;                       // 43008
    const int SM1 = 128*68*4 + 16*384*4;                       // 59392
    const int SM2 = 128*68*4 + 16*640*4;                       // 75776
    const int SMA = (64*PQ + 32*PQ + 144*PV + 64*PP) * 4;      // 95488

    cudaFuncSetAttribute((const void*)linear_kernel<0>, cudaFuncAttributeMaxDynamicSharedMemorySize, SM0);
    cudaFuncSetAttribute((const void*)linear_kernel<1>, cudaFuncAttributeMaxDynamicSharedMemorySize, SM1);
    cudaFuncSetAttribute((const void*)linear_kernel<2>, cudaFuncAttributeMaxDynamicSharedMemorySize, SM2);
    cudaFuncSetAttribute((const void*)attn_kernel,      cudaFuncAttributeMaxDynamicSharedMemorySize, SMA);

    rot_kernel<<<EE/256, 256>>>(ev, er, rotp);

    dim3 lgrid(NN/16, 2);
    linear_kernel<0><<<lgrid, 256, SM0>>>(x, Wq, qp);
    linear_kernel<1><<<lgrid, 256, SM1>>>(x, Wq, qp);
    linear_kernel<2><<<lgrid, 256, SM2>>>(x, Wq, qp);
    linear_kernel<0><<<lgrid, 256, SM0>>>(x, Wk, kp);
    linear_kernel<1><<<lgrid, 256, SM1>>>(x, Wk, kp);
    linear_kernel<2><<<lgrid, 256, SM2>>>(x, Wk, kp);
    linear_kernel<0><<<lgrid, 256, SM0>>>(x, Wv, vp);
    linear_kernel<1><<<lgrid, 256, SM1>>>(x, Wv, vp);
    linear_kernel<2><<<lgrid, 256, SM2>>>(x, Wv, vp);

    attn_kernel<<<dim3(8, 128), 128, SMA>>>(qp, kp, vp, op);

    linear_kernel<0><<<lgrid, 256, SM0>>>(op, Wo, kp);
    linear_kernel<1><<<lgrid, 256, SM1>>>(op, Wo, kp);
    linear_kernel<2><<<lgrid, 256, SM2>>>(op, Wo, kp);

    epilogue_kernel<<<NN, 256>>>(x, kp, gamma, beta, out);
}

// round 5
// speedup vs baseline: 1.9362x; 1.1982x over previous
#include <cuda_runtime.h>
#include <math.h>

#define NN 8192
#define DD 1152
#define EE 262144

typedef unsigned int uint32;
typedef unsigned long long ull;

// -------- scratch (allocation-free: static device globals) --------
__device__ float g_q[(size_t)NN * DD];
__device__ float g_k[(size_t)NN * DD];
__device__ float g_v[(size_t)NN * DD];
__device__ float g_o[(size_t)NN * DD];

// -------- tf32 mma helpers --------
__device__ __forceinline__ float tf32r(float x) {
    uint32 r; asm("cvt.rna.tf32.f32 %0, %1;" : "=r"(r) : "f"(x));
    return __uint_as_float(r);
}
__device__ __forceinline__ void mma_tf32(float* d,
                                         uint32 a0, uint32 a1, uint32 a2, uint32 a3,
                                         uint32 b0, uint32 b1) {
    asm("mma.sync.aligned.m16n8k8.row.col.f32.tf32.tf32.f32 "
        "{%0,%1,%2,%3}, {%4,%5,%6,%7}, {%8,%9}, {%0,%1,%2,%3};"
        : "+f"(d[0]), "+f"(d[1]), "+f"(d[2]), "+f"(d[3])
        : "r"(a0), "r"(a1), "r"(a2), "r"(a3), "r"(b0), "r"(b1));
}

// ====================== rot kernel ======================
__global__ void rot_kernel(const float* __restrict__ ev,
                           const float* __restrict__ er,
                           float* __restrict__ rot)
{
    int e = blockIdx.x * 256 + threadIdx.x;
    if (e >= EE) return;
    float vx = ev[3*e+0], vy = ev[3*e+1], vz = ev[3*e+2];
    float dist = sqrtf(vx*vx + vy*vy + vz*vz);
    float nx0 = vx/dist, nx1 = vy/dist, nx2 = vz/dist;

    float r0 = er[3*e+0]-0.5f, r1 = er[3*e+1]-0.5f, r2 = er[3*e+2]-0.5f;
    float rn = sqrtf(r0*r0 + r1*r1 + r2*r2);
    float a0 = r0/rn, a1 = r1/rn, a2 = r2/rn;
    float b0 = -a1, b1 = a0, b2 = a2;
    float c0 = a0, c1 = -a2, c2 = a1;

    float da = fabsf(a0*nx0 + a1*nx1 + a2*nx2);
    float db = fabsf(b0*nx0 + b1*nx1 + b2*nx2);
    float dc = fabsf(c0*nx0 + c1*nx1 + c2*nx2);

    float e0 = a0, e1 = a1, e2c_ = a2, dcur = da;
    if (dcur > db) { e0 = b0; e1 = b1; e2c_ = b2; dcur = db; }
    if (dcur > dc) { e0 = c0; e1 = c1; e2c_ = c2; }

    float z0 = nx1*e2c_ - nx2*e1;
    float z1 = nx2*e0   - nx0*e2c_;
    float z2 = nx0*e1   - nx1*e0;
    float zn = sqrtf(z0*z0 + z1*z1 + z2*z2);
    z0 /= zn; z1 /= zn; z2 /= zn;
    float y0 = nx1*z2 - nx2*z1;
    float y1 = nx2*z0 - nx0*z2;
    float y2 = nx0*z1 - nx1*z0;
    float yn = sqrtf(y0*y0 + y1*y1 + y2*y2);
    y0 /= yn; y1 /= yn; y2 /= yn;

    float* R = rot + (size_t)e * 9;
    R[0] =  z0; R[1] =  z1; R[2] =  z2;
    R[3] = nx0; R[4] = nx1; R[5] = nx2;
    R[6] = -y0; R[7] = -y1; R[8] = -y2;
}

// ====================== irreps linear (TF32 mma) ======================
// Per-l GEMM: A[(n*d+m)][c] = x[n, s+c*d+m] (R x 128), B = W[o][c] (128 x 128).
// Block: 256 thr = 8 warps (4 row-tiles x 2 col-tiles); tile 64 rows x 128 outs.
// Pitch 132 (== 4 mod 32): mma frag loads conflict-free (verified pattern in attn).
#define PL 132
template<int L>
__global__ void __launch_bounds__(256) linear_tf32(const float* __restrict__ x,
                                                   const float* __restrict__ W,
                                                   float* __restrict__ y)
{
    constexpr int d = 2*L + 1;
    constexpr int s = (L == 0) ? 0 : (L == 1 ? 128 : 512);

    extern __shared__ float sm[];
    float* As = sm;             // [64][132]
    float* Bs = sm + 64*PL;     // [128][132]  Bs[o][c] = tf32(W[l][o][c])

    const int tid  = threadIdx.x;
    const int wid  = tid >> 5, lane = tid & 31;
    const int gr   = lane >> 2, th = lane & 3;
    const int wr   = wid >> 1, wc = wid & 1;       // 4 row-warps x 2 col-warps
    const int warpRow = wr * 16;
    const int colBase = wc * 64;
    const int r0   = blockIdx.x * 64;

    // --- fill W (tf32) ---
    const float* Wl = W + L * 16384;
    for (int idx = tid; idx < 4096; idx += 256) {
        int o = idx >> 5, c4 = (idx & 31) * 4;
        float4 w4 = *(const float4*)&Wl[o*128 + c4];
        Bs[o*PL + c4+0] = tf32r(w4.x);
        Bs[o*PL + c4+1] = tf32r(w4.y);
        Bs[o*PL + c4+2] = tf32r(w4.z);
        Bs[o*PL + c4+3] = tf32r(w4.w);
    }
    // --- fill A (gathered, rows inner so lanes hit nearby lines) ---
    for (int i = tid; i < 64*128; i += 256) {
        int row = i & 63, c = i >> 6;
        int rg = r0 + row;
        int n = rg / d, m = rg - n * d;
        As[row*PL + c] = tf32r(__ldg(&x[(size_t)n*DD + s + c*d + m]));
    }
    __syncthreads();

    // --- mma mainloop: 16 k-steps ---
    float acc[8][4];
    #pragma unroll
    for (int nt = 0; nt < 8; nt++)
        #pragma unroll
        for (int j = 0; j < 4; j++) acc[nt][j] = 0.f;

    #pragma unroll 4
    for (int ks = 0; ks < 16; ks++) {
        int k0 = ks * 8;
        const float* Ar = As + k0 + th;
        uint32 a0 = __float_as_uint(Ar[(warpRow + gr    ) * PL    ]);
        uint32 a1 = __float_as_uint(Ar[(warpRow + gr + 8) * PL    ]);
        uint32 a2 = __float_as_uint(Ar[(warpRow + gr    ) * PL + 4]);
        uint32 a3 = __float_as_uint(Ar[(warpRow + gr + 8) * PL + 4]);
        #pragma unroll
        for (int nt = 0; nt < 8; nt++) {
            const float* Br = Bs + (colBase + nt*8 + gr) * PL + k0 + th;
            uint32 b0 = __float_as_uint(Br[0]);
            uint32 b1 = __float_as_uint(Br[4]);
            mma_tf32(acc[nt], a0, a1, a2, a3, b0, b1);
        }
    }

    // --- epilogue: scale + scattered store ---
    const float scale = 0.08838834764831845f;  // 1/sqrt(128)
    #pragma unroll
    for (int r = 0; r < 2; r++) {
        int rg = r0 + warpRow + gr + 8*r;
        int n = rg / d, m = rg - n * d;
        float* yb = y + (size_t)n*DD + s + m;
        #pragma unroll
        for (int nt = 0; nt < 8; nt++) {
            int o = colBase + nt*8 + 2*th;
            yb[(o  )*d] = acc[nt][2*r  ] * scale;
            yb[(o+1)*d] = acc[nt][2*r+1] * scale;
        }
    }
}

// ====================== flash attention (TF32 mma.sync, R4-verified) ======================
#define PQ 148
#define PV 44
#define PP 52

__global__ void __launch_bounds__(128) attn_kernel(const float* __restrict__ q,
                                                   const float* __restrict__ k,
                                                   const float* __restrict__ v,
                                                   float* __restrict__ o)
{
    extern __shared__ float sm[];
    float* Qs  = sm;               // [64][148]
    float* Ks  = Qs  + 64*PQ;      // [32][148]
    float* VsT = Ks  + 32*PQ;      // [144][44]
    float* Ps  = VsT + 144*PV;     // [64][52]

    const int tid  = threadIdx.x;
    const int wid  = tid >> 5, lane = tid & 31;
    const int gr   = lane >> 2, th = lane & 3;
    const int b    = blockIdx.y >> 3, h = blockIdx.y & 7;
    const int q0   = blockIdx.x * 64;
    const size_t hoff  = (size_t)h * 144;
    const size_t bbase = (size_t)b * 512;

    const float qscale = 1.0f / 12.0f;
    for (int f = tid; f < 64*36; f += 128) {
        int row = f / 36, cs = (f % 36) * 4;
        float4 qa = *(const float4*)&q[(bbase + q0 + row) * DD + hoff + cs];
        Qs[row*PQ + cs+0] = tf32r(qa.x * qscale);
        Qs[row*PQ + cs+1] = tf32r(qa.y * qscale);
        Qs[row*PQ + cs+2] = tf32r(qa.z * qscale);
        Qs[row*PQ + cs+3] = tf32r(qa.w * qscale);
    }

    float m_i[2] = {-1e30f, -1e30f};
    float l_i[2] = {0.f, 0.f};
    float oac[18][4];
    #pragma unroll
    for (int nt = 0; nt < 18; nt++)
        #pragma unroll
        for (int j = 0; j < 4; j++) oac[nt][j] = 0.f;

    const int warpRow = 16 * wid;

    for (int kt = 0; kt < 512; kt += 32) {
        __syncthreads();
        for (int f = tid; f < 32*36; f += 128) {
            int row = f / 36, cs = (f % 36) * 4;
            size_t g = (bbase + kt + row) * (size_t)DD + hoff + cs;
            float4 ka = *(const float4*)&k[g];
            Ks[row*PQ + cs+0] = tf32r(ka.x);
            Ks[row*PQ + cs+1] = tf32r(ka.y);
            Ks[row*PQ + cs+2] = tf32r(ka.z);
            Ks[row*PQ + cs+3] = tf32r(ka.w);
            float4 va = *(const float4*)&v[g];
            VsT[(cs+0)*PV + row] = tf32r(va.x);
            VsT[(cs+1)*PV + row] = tf32r(va.y);
            VsT[(cs+2)*PV + row] = tf32r(va.z);
            VsT[(cs+3)*PV + row] = tf32r(va.w);
        }
        __syncthreads();

        float s_[4][4];
        #pragma unroll
        for (int nt = 0; nt < 4; nt++)
            #pragma unroll
            for (int j = 0; j < 4; j++) s_[nt][j] = 0.f;

        #pragma unroll 3
        for (int ks = 0; ks < 18; ks++) {
            int k0 = ks * 8;
            const float* Qr = Qs + k0 + th;
            uint32 a0 = __float_as_uint(Qr[(warpRow + gr     ) * PQ    ]);
            uint32 a1 = __float_as_uint(Qr[(warpRow + gr + 8 ) * PQ    ]);
            uint32 a2 = __float_as_uint(Qr[(warpRow + gr     ) * PQ + 4]);
            uint32 a3 = __float_as_uint(Qr[(warpRow + gr + 8 ) * PQ + 4]);
            #pragma unroll
            for (int nt = 0; nt < 4; nt++) {
                const float* Kr = Ks + (nt*8 + gr) * PQ + k0 + th;
                uint32 b0 = __float_as_uint(Kr[0]);
                uint32 b1 = __float_as_uint(Kr[4]);
                mma_tf32(s_[nt], a0, a1, a2, a3, b0, b1);
            }
        }

        #pragma unroll
        for (int r = 0; r < 2; r++) {
            float rm = -1e30f;
            #pragma unroll
            for (int nt = 0; nt < 4; nt++)
                rm = fmaxf(rm, fmaxf(s_[nt][2*r], s_[nt][2*r+1]));
            rm = fmaxf(rm, __shfl_xor_sync(0xffffffffu, rm, 1));
            rm = fmaxf(rm, __shfl_xor_sync(0xffffffffu, rm, 2));
            float newm = fmaxf(m_i[r], rm);
            float rs = 0.f;
            #pragma unroll
            for (int nt = 0; nt < 4; nt++) {
                float p0 = __expf(s_[nt][2*r  ] - newm);
                float p1 = __expf(s_[nt][2*r+1] - newm);
                s_[nt][2*r] = p0; s_[nt][2*r+1] = p1;
                rs += p0 + p1;
            }
            rs += __shfl_xor_sync(0xffffffffu, rs, 1);
            rs += __shfl_xor_sync(0xffffffffu, rs, 2);
            float corr = __expf(m_i[r] - newm);
            l_i[r] = l_i[r] * corr + rs;
            m_i[r] = newm;
            #pragma unroll
            for (int nt = 0; nt < 18; nt++) {
                oac[nt][2*r  ] *= corr;
                oac[nt][2*r+1] *= corr;
            }
        }

        #pragma unroll
        for (int nt = 0; nt < 4; nt++) {
            int col = nt*8 + 2*th;
            Ps[(warpRow + gr    ) * PP + col    ] = tf32r(s_[nt][0]);
            Ps[(warpRow + gr    ) * PP + col + 1] = tf32r(s_[nt][1]);
            Ps[(warpRow + gr + 8) * PP + col    ] = tf32r(s_[nt][2]);
            Ps[(warpRow + gr + 8) * PP + col + 1] = tf32r(s_[nt][3]);
        }
        __syncwarp();

        #pragma unroll
        for (int ks = 0; ks < 4; ks++) {
            int k0 = ks * 8;
            const float* Pr = Ps + k0 + th;
            uint32 a0 = __float_as_uint(Pr[(warpRow + gr    ) * PP    ]);
            uint32 a1 = __float_as_uint(Pr[(warpRow + gr + 8) * PP    ]);
            uint32 a2 = __float_as_uint(Pr[(warpRow + gr    ) * PP + 4]);
            uint32 a3 = __float_as_uint(Pr[(warpRow + gr + 8) * PP + 4]);
            #pragma unroll
            for (int nt = 0; nt < 18; nt++) {
                const float* Vr = VsT + (nt*8 + gr) * PV + k0 + th;
                uint32 b0 = __float_as_uint(Vr[0]);
                uint32 b1 = __float_as_uint(Vr[4]);
                mma_tf32(oac[nt], a0, a1, a2, a3, b0, b1);
            }
        }
    }

    #pragma unroll
    for (int r = 0; r < 2; r++) {
        float inv = 1.0f / l_i[r];
        int row = q0 + warpRow + gr + 8*r;
        float* ob = o + (bbase + row) * (size_t)DD + hoff;
        #pragma unroll
        for (int nt = 0; nt < 18; nt++) {
            int col = nt*8 + 2*th;
            ob[col    ] = oac[nt][2*r  ] * inv;
            ob[col + 1] = oac[nt][2*r+1] * inv;
        }
    }
}

// ====================== epilogue ======================
__global__ void __launch_bounds__(256) epilogue_kernel(const float* __restrict__ x,
                                                       const float* __restrict__ attn,
                                                       const float* __restrict__ gamma,
                                                       const float* __restrict__ beta,
                                                       float* __restrict__ out)
{
    const int n = blockIdx.x;
    const int tid = threadIdx.x;
    const size_t base = (size_t)n * DD;

    __shared__ float red[8];
    __shared__ float mu_s, rv_s;

    float val = 0.f;
    if (tid < 128) val = x[base + tid] + attn[base + tid];
    float s1 = val, s2 = val * val;
    #pragma unroll
    for (int off = 16; off; off >>= 1) {
        s1 += __shfl_xor_sync(0xffffffffu, s1, off);
        s2 += __shfl_xor_sync(0xffffffffu, s2, off);
    }
    if (tid < 128 && (tid & 31) == 0) { red[(tid>>5)*2] = s1; red[(tid>>5)*2+1] = s2; }
    __syncthreads();
    if (tid == 0) {
        float t1 = red[0] + red[2] + red[4] + red[6];
        float t2 = red[1] + red[3] + red[5] + red[7];
        float mu = t1 * (1.f/128.f);
        float var = t2 * (1.f/128.f) - mu*mu;
        mu_s = mu;
        rv_s = rsqrtf(var + 1e-5f);
    }
    __syncthreads();
    const float mu = mu_s, rv = rv_s;

    for (int i = tid; i < DD; i += 256) {
        float vv = x[base + i] + attn[base + i];
        if (i < 128) {
            float z = (vv - mu) * rv * gamma[i] + beta[i];
            vv = z / (1.f + __expf(-z));
        }
        out[base + i] = vv;
    }
}

// ====================== launch ======================
extern "C" void kernel_launch(void* const* d_in, const int* in_sizes, int n_in,
                              void* d_out, int out_size)
{
    const float* x     = (const float*)d_in[0];
    const float* ev    = (const float*)d_in[1];
    const float* er    = (const float*)d_in[2];
    const float* Wq    = (const float*)d_in[3];
    const float* Wk    = (const float*)d_in[4];
    const float* Wv    = (const float*)d_in[5];
    const float* Wo    = (const float*)d_in[6];
    const float* gamma = (const float*)d_in[7];
    const float* beta  = (const float*)d_in[8];
    float* out  = (float*)d_out;
    float* rotp = out + (size_t)NN * DD;

    float *qp, *kp, *vp, *op;
    cudaGetSymbolAddress((void**)&qp, g_q);
    cudaGetSymbolAddress((void**)&kp, g_k);
    cudaGetSymbolAddress((void**)&vp, g_v);
    cudaGetSymbolAddress((void**)&op, g_o);

    const int SML = (64*PL + 128*PL) * 4;                      // 101376
    const int SMA = (64*PQ + 32*PQ + 144*PV + 64*PP) * 4;      // 95488

    cudaFuncSetAttribute((const void*)linear_tf32<0>, cudaFuncAttributeMaxDynamicSharedMemorySize, SML);
    cudaFuncSetAttribute((const void*)linear_tf32<1>, cudaFuncAttributeMaxDynamicSharedMemorySize, SML);
    cudaFuncSetAttribute((const void*)linear_tf32<2>, cudaFuncAttributeMaxDynamicSharedMemorySize, SML);
    cudaFuncSetAttribute((const void*)attn_kernel,    cudaFuncAttributeMaxDynamicSharedMemorySize, SMA);

    rot_kernel<<<EE/256, 256>>>(ev, er, rotp);

    // rows per l: 8192*d / 64-row tiles
    linear_tf32<0><<<128, 256, SML>>>(x, Wq, qp);
    linear_tf32<1><<<384, 256, SML>>>(x, Wq, qp);
    linear_tf32<2><<<640, 256, SML>>>(x, Wq, qp);
    linear_tf32<0><<<128, 256, SML>>>(x, Wk, kp);
    linear_tf32<1><<<384, 256, SML>>>(x, Wk, kp);
    linear_tf32<2><<<640, 256, SML>>>(x, Wk, kp);
    linear_tf32<0><<<128, 256, SML>>>(x, Wv, vp);
    linear_tf32<1><<<384, 256, SML>>>(x, Wv, vp);
    linear_tf32<2><<<640, 256, SML>>>(x, Wv, vp);

    attn_kernel<<<dim3(8, 128), 128, SMA>>>(qp, kp, vp, op);

    linear_tf32<0><<<128, 256, SML>>>(op, Wo, kp);
    linear_tf32<1><<<384, 256, SML>>>(op, Wo, kp);
    linear_tf32<2><<<640, 256, SML>>>(op, Wo, kp);

    epilogue_kernel<<<NN, 256>>>(x, kp, gamma, beta, out);
}

// round 6
// speedup vs baseline: 2.9749x; 1.5365x over previous
#include <cuda_runtime.h>
#include <math.h>

#define NN 8192
#define DD 1152
#define EE 262144

typedef unsigned int uint32;

// -------- scratch (allocation-free: static device globals) --------
__device__ float g_q[(size_t)NN * DD];
__device__ float g_k[(size_t)NN * DD];
__device__ float g_v[(size_t)NN * DD];
__device__ float g_o[(size_t)NN * DD];

// -------- tf32 mma helper (HW reads regs as tf32; low bits ignored) --------
__device__ __forceinline__ void mma_tf32(float* d,
                                         uint32 a0, uint32 a1, uint32 a2, uint32 a3,
                                         uint32 b0, uint32 b1) {
    asm("mma.sync.aligned.m16n8k8.row.col.f32.tf32.tf32.f32 "
        "{%0,%1,%2,%3}, {%4,%5,%6,%7}, {%8,%9}, {%0,%1,%2,%3};"
        : "+f"(d[0]), "+f"(d[1]), "+f"(d[2]), "+f"(d[3])
        : "r"(a0), "r"(a1), "r"(a2), "r"(a3), "r"(b0), "r"(b1));
}

// -------- cp.async helpers --------
__device__ __forceinline__ void cp16(void* smem, const void* gmem) {
    uint32 s = (uint32)__cvta_generic_to_shared(smem);
    asm volatile("cp.async.cg.shared.global [%0], [%1], 16;" :: "r"(s), "l"(gmem));
}
__device__ __forceinline__ void cp_commit() { asm volatile("cp.async.commit_group;"); }
__device__ __forceinline__ void cp_wait0()  { asm volatile("cp.async.wait_group 0;"); }

// ====================== rot kernel ======================
__global__ void rot_kernel(const float* __restrict__ ev,
                           const float* __restrict__ er,
                           float* __restrict__ rot)
{
    int e = blockIdx.x * 256 + threadIdx.x;
    if (e >= EE) return;
    float vx = ev[3*e+0], vy = ev[3*e+1], vz = ev[3*e+2];
    float dist = sqrtf(vx*vx + vy*vy + vz*vz);
    float nx0 = vx/dist, nx1 = vy/dist, nx2 = vz/dist;

    float r0 = er[3*e+0]-0.5f, r1 = er[3*e+1]-0.5f, r2 = er[3*e+2]-0.5f;
    float rn = sqrtf(r0*r0 + r1*r1 + r2*r2);
    float a0 = r0/rn, a1 = r1/rn, a2 = r2/rn;
    float b0 = -a1, b1 = a0, b2 = a2;
    float c0 = a0, c1 = -a2, c2 = a1;

    float da = fabsf(a0*nx0 + a1*nx1 + a2*nx2);
    float db = fabsf(b0*nx0 + b1*nx1 + b2*nx2);
    float dc = fabsf(c0*nx0 + c1*nx1 + c2*nx2);

    float e0 = a0, e1 = a1, e2c_ = a2, dcur = da;
    if (dcur > db) { e0 = b0; e1 = b1; e2c_ = b2; dcur = db; }
    if (dcur > dc) { e0 = c0; e1 = c1; e2c_ = c2; }

    float z0 = nx1*e2c_ - nx2*e1;
    float z1 = nx2*e0   - nx0*e2c_;
    float z2 = nx0*e1   - nx1*e0;
    float zn = sqrtf(z0*z0 + z1*z1 + z2*z2);
    z0 /= zn; z1 /= zn; z2 /= zn;
    float y0 = nx1*z2 - nx2*z1;
    float y1 = nx2*z0 - nx0*z2;
    float y2 = nx0*z1 - nx1*z0;
    float yn = sqrtf(y0*y0 + y1*y1 + y2*y2);
    y0 /= yn; y1 /= yn; y2 /= yn;

    float* R = rot + (size_t)e * 9;
    R[0] =  z0; R[1] =  z1; R[2] =  z2;
    R[3] = nx0; R[4] = nx1; R[5] = nx2;
    R[6] = -y0; R[7] = -y1; R[8] = -y2;
}

#define PL 132

// ====================== fused QKV linear (TF32 mma, W-resident) ======================
// Block covers 32 output-cols (blockIdx.y) x 3 weights, loops row-tiles of 64.
// 256 thr = 8 warps = 4 row x 2 col; warp: 16 rows x 16 cols x 3 weights.
template<int L>
__global__ void __launch_bounds__(256) qkv_tf32(const float* __restrict__ x,
                                                const float* __restrict__ Wq,
                                                const float* __restrict__ Wk,
                                                const float* __restrict__ Wv,
                                                float* __restrict__ q,
                                                float* __restrict__ k,
                                                float* __restrict__ v)
{
    constexpr int d = 2*L + 1;
    constexpr int s = (L == 0) ? 0 : (L == 1 ? 128 : 512);
    constexpr int ntiles = (NN * d) / 64;

    extern __shared__ float sm[];
    float* As = sm;             // [64][132]
    float* Bs = sm + 64*PL;     // [3][32][132]

    const int tid  = threadIdx.x;
    const int lane = tid & 31, wid = tid >> 5;
    const int gr   = lane >> 2, th = lane & 3;
    const int wr   = wid >> 1, wc = wid & 1;
    const int obase = blockIdx.y * 32;

    // --- W fill (once, cp.async raw) ---
    for (int i = tid; i < 3*32*32; i += 256) {
        int wi = i >> 10, rem = i & 1023;
        int o = rem >> 5, c4 = (rem & 31) * 4;
        const float* wp = (wi == 0) ? Wq : (wi == 1 ? Wk : Wv);
        cp16(&Bs[(wi*32 + o)*PL + c4], &wp[(obase + o)*128 + c4]);
    }
    cp_commit();

    const float scale = 0.08838834764831845f;  // 1/sqrt(128)

    for (int t = blockIdx.x; t < ntiles; t += gridDim.x) {
        const int r0 = t * 64;
        __syncthreads();   // protect As from previous iteration's readers
        for (int i = tid; i < 64*128; i += 256) {
            int row = i & 63, c = i >> 6;
            int rg = r0 + row;
            int n = rg / d, m = rg - n * d;
            As[row*PL + c] = __ldg(&x[(size_t)n*DD + s + c*d + m]);
        }
        cp_wait0();        // W ready (no-op after first tile)
        __syncthreads();

        float acc[3][2][4];
        #pragma unroll
        for (int wi = 0; wi < 3; wi++)
            #pragma unroll
            for (int nt = 0; nt < 2; nt++)
                #pragma unroll
                for (int j = 0; j < 4; j++) acc[wi][nt][j] = 0.f;

        #pragma unroll 4
        for (int ks = 0; ks < 16; ks++) {
            int k0 = ks * 8;
            const float* Ar = As + k0 + th;
            uint32 a0 = __float_as_uint(Ar[(wr*16 + gr    ) * PL    ]);
            uint32 a1 = __float_as_uint(Ar[(wr*16 + gr + 8) * PL    ]);
            uint32 a2 = __float_as_uint(Ar[(wr*16 + gr    ) * PL + 4]);
            uint32 a3 = __float_as_uint(Ar[(wr*16 + gr + 8) * PL + 4]);
            #pragma unroll
            for (int wi = 0; wi < 3; wi++)
                #pragma unroll
                for (int nt = 0; nt < 2; nt++) {
                    const float* Br = Bs + (wi*32 + wc*16 + nt*8 + gr)*PL + k0 + th;
                    uint32 b0 = __float_as_uint(Br[0]);
                    uint32 b1 = __float_as_uint(Br[4]);
                    mma_tf32(acc[wi][nt], a0, a1, a2, a3, b0, b1);
                }
        }

        #pragma unroll
        for (int wi = 0; wi < 3; wi++) {
            float* yp = (wi == 0) ? q : (wi == 1 ? k : v);
            #pragma unroll
            for (int r = 0; r < 2; r++) {
                int rg = r0 + wr*16 + gr + 8*r;
                int n = rg / d, m = rg - n * d;
                float* yb = yp + (size_t)n*DD + s + m;
                #pragma unroll
                for (int nt = 0; nt < 2; nt++) {
                    int o = obase + wc*16 + nt*8 + 2*th;
                    yb[(o  )*d] = acc[wi][nt][2*r  ] * scale;
                    yb[(o+1)*d] = acc[wi][nt][2*r+1] * scale;
                }
            }
        }
    }
}

// ====================== single linear (W_o path; R5-proven minus cvts) ======================
template<int L>
__global__ void __launch_bounds__(256) linear_tf32(const float* __restrict__ x,
                                                   const float* __restrict__ W,
                                                   float* __restrict__ y)
{
    constexpr int d = 2*L + 1;
    constexpr int s = (L == 0) ? 0 : (L == 1 ? 128 : 512);

    extern __shared__ float sm[];
    float* As = sm;             // [64][132]
    float* Bs = sm + 64*PL;     // [128][132]

    const int tid  = threadIdx.x;
    const int wid  = tid >> 5, lane = tid & 31;
    const int gr   = lane >> 2, th = lane & 3;
    const int wr   = wid >> 1, wc = wid & 1;
    const int warpRow = wr * 16;
    const int colBase = wc * 64;
    const int r0   = blockIdx.x * 64;

    const float* Wl = W + L * 16384;
    for (int idx = tid; idx < 32*32; idx += 256) {
        int o = idx >> 3, c4 = (idx & 7) * 16;   // 128 rows x 8 chunks... recompute
        (void)o; (void)c4;
    }
    // W fill: 128 rows x 32 16B-chunks = 4096 cp.async
    for (int i = tid; i < 4096; i += 256) {
        int o = i >> 5, c4 = (i & 31) * 4;
        cp16(&Bs[o*PL + c4], &Wl[o*128 + c4]);
    }
    cp_commit();

    for (int i = tid; i < 64*128; i += 256) {
        int row = i & 63, c = i >> 6;
        int rg = r0 + row;
        int n = rg / d, m = rg - n * d;
        As[row*PL + c] = __ldg(&x[(size_t)n*DD + s + c*d + m]);
    }
    cp_wait0();
    __syncthreads();

    float acc[8][4];
    #pragma unroll
    for (int nt = 0; nt < 8; nt++)
        #pragma unroll
        for (int j = 0; j < 4; j++) acc[nt][j] = 0.f;

    #pragma unroll 4
    for (int ks = 0; ks < 16; ks++) {
        int k0 = ks * 8;
        const float* Ar = As + k0 + th;
        uint32 a0 = __float_as_uint(Ar[(warpRow + gr    ) * PL    ]);
        uint32 a1 = __float_as_uint(Ar[(warpRow + gr + 8) * PL    ]);
        uint32 a2 = __float_as_uint(Ar[(warpRow + gr    ) * PL + 4]);
        uint32 a3 = __float_as_uint(Ar[(warpRow + gr + 8) * PL + 4]);
        #pragma unroll
        for (int nt = 0; nt < 8; nt++) {
            const float* Br = Bs + (colBase + nt*8 + gr) * PL + k0 + th;
            uint32 b0 = __float_as_uint(Br[0]);
            uint32 b1 = __float_as_uint(Br[4]);
            mma_tf32(acc[nt], a0, a1, a2, a3, b0, b1);
        }
    }

    const float scale = 0.08838834764831845f;
    #pragma unroll
    for (int r = 0; r < 2; r++) {
        int rg = r0 + warpRow + gr + 8*r;
        int n = rg / d, m = rg - n * d;
        float* yb = y + (size_t)n*DD + s + m;
        #pragma unroll
        for (int nt = 0; nt < 8; nt++) {
            int o = colBase + nt*8 + 2*th;
            yb[(o  )*d] = acc[nt][2*r  ] * scale;
            yb[(o+1)*d] = acc[nt][2*r+1] * scale;
        }
    }
}

// ====================== flash attention (TF32, cp.async fills) ======================
#define PQ 148
#define PVP 152
#define PP 52

__global__ void __launch_bounds__(128) attn_kernel(const float* __restrict__ q,
                                                   const float* __restrict__ k,
                                                   const float* __restrict__ v,
                                                   float* __restrict__ o)
{
    extern __shared__ float sm[];
    float* Qs = sm;               // [64][148]
    float* Ks = Qs + 64*PQ;       // [32][148]
    float* Vs = Ks + 32*PQ;       // [32][152]  natural [key][dim]
    float* Ps = Vs + 32*PVP;      // [64][52]

    const int tid  = threadIdx.x;
    const int wid  = tid >> 5, lane = tid & 31;
    const int gr   = lane >> 2, th = lane & 3;
    const int b    = blockIdx.y >> 3, h = blockIdx.y & 7;
    const int q0   = blockIdx.x * 64;
    const size_t hoff  = (size_t)h * 144;
    const size_t bbase = (size_t)b * 512;
    const float qscale = 1.0f / 12.0f;

    // Q fill (raw, cp.async)
    for (int f = tid; f < 64*36; f += 128) {
        int row = f / 36, cs = (f % 36) * 4;
        cp16(&Qs[row*PQ + cs], &q[(bbase + q0 + row) * DD + hoff + cs]);
    }
    cp_commit();

    float m_i[2] = {-1e30f, -1e30f};
    float l_i[2] = {0.f, 0.f};
    float oac[18][4];
    #pragma unroll
    for (int nt = 0; nt < 18; nt++)
        #pragma unroll
        for (int j = 0; j < 4; j++) oac[nt][j] = 0.f;

    const int warpRow = 16 * wid;

    for (int kt = 0; kt < 512; kt += 32) {
        __syncthreads();
        for (int f = tid; f < 32*36; f += 128) {
            int row = f / 36, cs = (f % 36) * 4;
            size_t g = (bbase + kt + row) * (size_t)DD + hoff + cs;
            cp16(&Ks[row*PQ  + cs], &k[g]);
            cp16(&Vs[row*PVP + cs], &v[g]);
        }
        cp_commit();
        cp_wait0();
        __syncthreads();

        // ---- S = Q K^T ----
        float s_[4][4];
        #pragma unroll
        for (int nt = 0; nt < 4; nt++)
            #pragma unroll
            for (int j = 0; j < 4; j++) s_[nt][j] = 0.f;

        #pragma unroll 3
        for (int ks = 0; ks < 18; ks++) {
            int k0 = ks * 8;
            const float* Qr = Qs + k0 + th;
            uint32 a0 = __float_as_uint(Qr[(warpRow + gr    ) * PQ    ]);
            uint32 a1 = __float_as_uint(Qr[(warpRow + gr + 8) * PQ    ]);
            uint32 a2 = __float_as_uint(Qr[(warpRow + gr    ) * PQ + 4]);
            uint32 a3 = __float_as_uint(Qr[(warpRow + gr + 8) * PQ + 4]);
            #pragma unroll
            for (int nt = 0; nt < 4; nt++) {
                const float* Kr = Ks + (nt*8 + gr) * PQ + k0 + th;
                uint32 b0 = __float_as_uint(Kr[0]);
                uint32 b1 = __float_as_uint(Kr[4]);
                mma_tf32(s_[nt], a0, a1, a2, a3, b0, b1);
            }
        }

        // scale post-mma (Q was raw)
        #pragma unroll
        for (int nt = 0; nt < 4; nt++)
            #pragma unroll
            for (int j = 0; j < 4; j++) s_[nt][j] *= qscale;

        // ---- online softmax ----
        #pragma unroll
        for (int r = 0; r < 2; r++) {
            float rm = -1e30f;
            #pragma unroll
            for (int nt = 0; nt < 4; nt++)
                rm = fmaxf(rm, fmaxf(s_[nt][2*r], s_[nt][2*r+1]));
            rm = fmaxf(rm, __shfl_xor_sync(0xffffffffu, rm, 1));
            rm = fmaxf(rm, __shfl_xor_sync(0xffffffffu, rm, 2));
            float newm = fmaxf(m_i[r], rm);
            float rs = 0.f;
            #pragma unroll
            for (int nt = 0; nt < 4; nt++) {
                float p0 = __expf(s_[nt][2*r  ] - newm);
                float p1 = __expf(s_[nt][2*r+1] - newm);
                s_[nt][2*r] = p0; s_[nt][2*r+1] = p1;
                rs += p0 + p1;
            }
            rs += __shfl_xor_sync(0xffffffffu, rs, 1);
            rs += __shfl_xor_sync(0xffffffffu, rs, 2);
            float corr = __expf(m_i[r] - newm);
            l_i[r] = l_i[r] * corr + rs;
            m_i[r] = newm;
            #pragma unroll
            for (int nt = 0; nt < 18; nt++) {
                oac[nt][2*r  ] *= corr;
                oac[nt][2*r+1] *= corr;
            }
        }

        #pragma unroll
        for (int nt = 0; nt < 4; nt++) {
            int col = nt*8 + 2*th;
            Ps[(warpRow + gr    ) * PP + col    ] = s_[nt][0];
            Ps[(warpRow + gr    ) * PP + col + 1] = s_[nt][1];
            Ps[(warpRow + gr + 8) * PP + col    ] = s_[nt][2];
            Ps[(warpRow + gr + 8) * PP + col + 1] = s_[nt][3];
        }
        __syncwarp();

        // ---- O += P V (V natural layout; b0 = Vs[k0+th][nt*8+gr]) ----
        #pragma unroll
        for (int ks = 0; ks < 4; ks++) {
            int k0 = ks * 8;
            const float* Pr = Ps + k0 + th;
            uint32 a0 = __float_as_uint(Pr[(warpRow + gr    ) * PP    ]);
            uint32 a1 = __float_as_uint(Pr[(warpRow + gr + 8) * PP    ]);
            uint32 a2 = __float_as_uint(Pr[(warpRow + gr    ) * PP + 4]);
            uint32 a3 = __float_as_uint(Pr[(warpRow + gr + 8) * PP + 4]);
            const float* Vb = Vs + (k0 + th) * PVP + gr;
            #pragma unroll
            for (int nt = 0; nt < 18; nt++) {
                uint32 b0 = __float_as_uint(Vb[nt*8]);
                uint32 b1 = __float_as_uint(Vb[nt*8 + 4*PVP]);
                mma_tf32(oac[nt], a0, a1, a2, a3, b0, b1);
            }
        }
    }

    #pragma unroll
    for (int r = 0; r < 2; r++) {
        float inv = 1.0f / l_i[r];
        int row = q0 + warpRow + gr + 8*r;
        float* ob = o + (bbase + row) * (size_t)DD + hoff;
        #pragma unroll
        for (int nt = 0; nt < 18; nt++) {
            int col = nt*8 + 2*th;
            ob[col    ] = oac[nt][2*r  ] * inv;
            ob[col + 1] = oac[nt][2*r+1] * inv;
        }
    }
}

// ====================== epilogue ======================
__global__ void __launch_bounds__(256) epilogue_kernel(const float* __restrict__ x,
                                                       const float* __restrict__ attn,
                                                       const float* __restrict__ gamma,
                                                       const float* __restrict__ beta,
                                                       float* __restrict__ out)
{
    const int n = blockIdx.x;
    const int tid = threadIdx.x;
    const size_t base = (size_t)n * DD;

    __shared__ float red[8];
    __shared__ float mu_s, rv_s;

    float val = 0.f;
    if (tid < 128) val = x[base + tid] + attn[base + tid];
    float s1 = val, s2 = val * val;
    #pragma unroll
    for (int off = 16; off; off >>= 1) {
        s1 += __shfl_xor_sync(0xffffffffu, s1, off);
        s2 += __shfl_xor_sync(0xffffffffu, s2, off);
    }
    if (tid < 128 && (tid & 31) == 0) { red[(tid>>5)*2] = s1; red[(tid>>5)*2+1] = s2; }
    __syncthreads();
    if (tid == 0) {
        float t1 = red[0] + red[2] + red[4] + red[6];
        float t2 = red[1] + red[3] + red[5] + red[7];
        float mu = t1 * (1.f/128.f);
        float var = t2 * (1.f/128.f) - mu*mu;
        mu_s = mu;
        rv_s = rsqrtf(var + 1e-5f);
    }
    __syncthreads();
    const float mu = mu_s, rv = rv_s;

    for (int i = tid; i < DD; i += 256) {
        float vv = x[base + i] + attn[base + i];
        if (i < 128) {
            float z = (vv - mu) * rv * gamma[i] + beta[i];
            vv = z / (1.f + __expf(-z));
        }
        out[base + i] = vv;
    }
}

// ====================== launch ======================
extern "C" void kernel_launch(void* const* d_in, const int* in_sizes, int n_in,
                              void* d_out, int out_size)
{
    const float* x     = (const float*)d_in[0];
    const float* ev    = (const float*)d_in[1];
    const float* er    = (const float*)d_in[2];
    const float* Wq    = (const float*)d_in[3];
    const float* Wk    = (const float*)d_in[4];
    const float* Wv    = (const float*)d_in[5];
    const float* Wo    = (const float*)d_in[6];
    const float* gamma = (const float*)d_in[7];
    const float* beta  = (const float*)d_in[8];
    float* out  = (float*)d_out;
    float* rotp = out + (size_t)NN * DD;

    float *qp, *kp, *vp, *op;
    cudaGetSymbolAddress((void**)&qp, g_q);
    cudaGetSymbolAddress((void**)&kp, g_k);
    cudaGetSymbolAddress((void**)&vp, g_v);
    cudaGetSymbolAddress((void**)&op, g_o);

    const int SMF = (64*PL + 3*32*PL) * 4;                       // 84480
    const int SML = (64*PL + 128*PL) * 4;                        // 101376
    const int SMA = (64*PQ + 32*PQ + 32*PVP + 64*PP) * 4;        // 89600

    cudaFuncSetAttribute((const void*)qkv_tf32<0>,    cudaFuncAttributeMaxDynamicSharedMemorySize, SMF);
    cudaFuncSetAttribute((const void*)qkv_tf32<1>,    cudaFuncAttributeMaxDynamicSharedMemorySize, SMF);
    cudaFuncSetAttribute((const void*)qkv_tf32<2>,    cudaFuncAttributeMaxDynamicSharedMemorySize, SMF);
    cudaFuncSetAttribute((const void*)linear_tf32<0>, cudaFuncAttributeMaxDynamicSharedMemorySize, SML);
    cudaFuncSetAttribute((const void*)linear_tf32<1>, cudaFuncAttributeMaxDynamicSharedMemorySize, SML);
    cudaFuncSetAttribute((const void*)linear_tf32<2>, cudaFuncAttributeMaxDynamicSharedMemorySize, SML);
    cudaFuncSetAttribute((const void*)attn_kernel,    cudaFuncAttributeMaxDynamicSharedMemorySize, SMA);

    rot_kernel<<<EE/256, 256>>>(ev, er, rotp);

    // Weight-index offsets: per-l weight = W + L*16384; qkv kernel receives base-l pointers.
    qkv_tf32<0><<<dim3(32, 4), 256, SMF>>>(x, Wq,           Wk,           Wv,           qp, kp, vp);
    qkv_tf32<1><<<dim3(96, 4), 256, SMF>>>(x, Wq + 16384,   Wk + 16384,   Wv + 16384,   qp, kp, vp);
    qkv_tf32<2><<<dim3(80, 4), 256, SMF>>>(x, Wq + 32768,   Wk + 32768,   Wv + 32768,   qp, kp, vp);

    attn_kernel<<<dim3(8, 128), 128, SMA>>>(qp, kp, vp, op);

    linear_tf32<0><<<128, 256, SML>>>(op, Wo, kp);
    linear_tf32<1><<<384, 256, SML>>>(op, Wo, kp);
    linear_tf32<2><<<640, 256, SML>>>(op, Wo, kp);

    epilogue_kernel<<<NN, 256>>>(x, kp, gamma, beta, out);
}